// round 1
// baseline (speedup 1.0000x reference)
#include <cuda_runtime.h>

// MixtureOfExpertsNet: B=8.4M rows, E=4 experts, H=16 hidden, fp32.
// pred[b] = sum_e q_e * adj_e / sum_e q_e,  q_e = mask_e * 2^(l'_e - M)
// where l' are gating logits pre-scaled by log2(e), adj_e = relu(MLP_e(xf_e)).
// 0/0 -> NaN matches the reference's all-NaN-row behavior.

#define LOG2E 1.4426950408889634f

constexpr int NT = 256;   // threads per block
constexpr int R  = 2;     // rows per thread

// packed fp32x2 FMA (sm_100a): 2x fp32 FMA per issue slot on the fma pipe.
__device__ __forceinline__ float2 ffma2(float2 a, float2 b, float2 c) {
    float2 d;
    asm("{\n\t"
        ".reg .b64 ra, rb, rc, rd;\n\t"
        "mov.b64 ra, {%2, %3};\n\t"
        "mov.b64 rb, {%4, %5};\n\t"
        "mov.b64 rc, {%6, %7};\n\t"
        "fma.rn.f32x2 rd, ra, rb, rc;\n\t"
        "mov.b64 {%0, %1}, rd;\n\t"
        "}"
        : "=f"(d.x), "=f"(d.y)
        : "f"(a.x), "f"(a.y), "f"(b.x), "f"(b.y), "f"(c.x), "f"(c.y));
    return d;
}

__device__ __forceinline__ float ex2f(float x) {
    float r;
    asm("ex2.approx.ftz.f32 %0, %1;" : "=f"(r) : "f"(x));
    return r;
}

// One H-quad of an expert MLP: t = relu(x*w1 + b1); acc += t*w2 (packed pairs).
__device__ __forceinline__ float2 expert_quad(float2 xp, float4 w1, float4 b1,
                                              float4 w2, float2 acc) {
    float2 t0 = ffma2(xp, make_float2(w1.x, w1.y), make_float2(b1.x, b1.y));
    float2 t1 = ffma2(xp, make_float2(w1.z, w1.w), make_float2(b1.z, b1.w));
    t0.x = fmaxf(t0.x, 0.f); t0.y = fmaxf(t0.y, 0.f);   // alu pipe (FMNMX)
    t1.x = fmaxf(t1.x, 0.f); t1.y = fmaxf(t1.y, 0.f);
    acc = ffma2(t0, make_float2(w2.x, w2.y), acc);
    acc = ffma2(t1, make_float2(w2.z, w2.w), acc);
    return acc;
}

struct __align__(16) SW {
    float wg[16];     // Wg row-major, pre-scaled by log2e
    float bg[4];      // pre-scaled by log2e
    float b2[4];
    float pad[8];     // keep w1 16B-aligned at a nice offset
    float w1[4][16];
    float b1[4][16];
    float w2[4][16];
};

__global__ __launch_bounds__(NT)
void moe_kernel(const float4* __restrict__ x,
                const float* __restrict__ Wg, const float* __restrict__ bg,
                const float* __restrict__ W1, const float* __restrict__ b1,
                const float* __restrict__ W2, const float* __restrict__ b2,
                float* __restrict__ out, int n) {
    __shared__ SW s;
    const int tid = threadIdx.x;

    // cooperative weight staging (216 floats)
    if (tid < 16) s.wg[tid] = Wg[tid] * LOG2E;
    if (tid < 4) { s.bg[tid] = bg[tid] * LOG2E; s.b2[tid] = b2[tid]; }
    if (tid >= 32 && tid < 96)  { int i = tid - 32;  s.w1[i >> 4][i & 15] = W1[i]; }
    if (tid >= 96 && tid < 160) { int i = tid - 96;  s.b1[i >> 4][i & 15] = b1[i]; }
    if (tid >= 160 && tid < 224){ int i = tid - 160; s.w2[i >> 4][i & 15] = W2[i]; }
    __syncthreads();

    // persistent small weights in registers
    float wg[16], bgr[4], b2r[4];
#pragma unroll
    for (int i = 0; i < 16; i++) wg[i] = s.wg[i];
#pragma unroll
    for (int i = 0; i < 4; i++) { bgr[i] = s.bg[i]; b2r[i] = s.b2[i]; }

    const int T = gridDim.x * NT;           // total threads
    int r[R];
    float4 xv[R];
    bool ok[R];
#pragma unroll
    for (int rr = 0; rr < R; rr++) {
        r[rr] = blockIdx.x * NT + tid + rr * T;
        ok[rr] = (r[rr] < n);
        xv[rr] = make_float4(0.f, 0.f, 0.f, 0.f);
        if (ok[rr]) xv[rr] = __ldg(&x[r[rr]]);
    }

    float xf[R][4], q[R][4], num[R], den[R];

#pragma unroll
    for (int rr = 0; rr < R; rr++) {
        const float4 v = xv[rr];
        const bool m0 = (v.x == v.x), m1 = (v.y == v.y),
                   m2 = (v.z == v.z), m3 = (v.w == v.w);
        const float x0 = m0 ? v.x : 0.f;
        const float x1 = m1 ? v.y : 0.f;
        const float x2 = m2 ? v.z : 0.f;
        const float x3 = m3 ? v.w : 0.f;
        xf[rr][0] = x0; xf[rr][1] = x1; xf[rr][2] = x2; xf[rr][3] = x3;

        // gating logits in log2 domain
        float l0 = fmaf(wg[0],  x0, fmaf(wg[1],  x1, fmaf(wg[2],  x2, fmaf(wg[3],  x3, bgr[0]))));
        float l1 = fmaf(wg[4],  x0, fmaf(wg[5],  x1, fmaf(wg[6],  x2, fmaf(wg[7],  x3, bgr[1]))));
        float l2 = fmaf(wg[8],  x0, fmaf(wg[9],  x1, fmaf(wg[10], x2, fmaf(wg[11], x3, bgr[2]))));
        float l3 = fmaf(wg[12], x0, fmaf(wg[13], x1, fmaf(wg[14], x2, fmaf(wg[15], x3, bgr[3]))));
        const float M = fmaxf(fmaxf(l0, l1), fmaxf(l2, l3));

        q[rr][0] = m0 ? ex2f(l0 - M) : 0.f;
        q[rr][1] = m1 ? ex2f(l1 - M) : 0.f;
        q[rr][2] = m2 ? ex2f(l2 - M) : 0.f;
        q[rr][3] = m3 ? ex2f(l3 - M) : 0.f;
        num[rr] = 0.f;
        den[rr] = 0.f;
    }

    // expert MLPs: weights loaded once per expert, applied to R rows
#pragma unroll
    for (int e = 0; e < 4; e++) {
        const float4* w1q = reinterpret_cast<const float4*>(&s.w1[e][0]);
        const float4* b1q = reinterpret_cast<const float4*>(&s.b1[e][0]);
        const float4* w2q = reinterpret_cast<const float4*>(&s.w2[e][0]);
        const float4 w1a = w1q[0], w1b = w1q[1], w1c = w1q[2], w1d = w1q[3];
        const float4 b1a = b1q[0], b1b = b1q[1], b1c = b1q[2], b1d = b1q[3];
        const float4 w2a = w2q[0], w2b = w2q[1], w2c = w2q[2], w2d = w2q[3];
        const float b2e = b2r[e];
#pragma unroll
        for (int rr = 0; rr < R; rr++) {
            const float xe = xf[rr][e];
            const float2 xp = make_float2(xe, xe);
            float2 acc = make_float2(0.f, 0.f);
            acc = expert_quad(xp, w1a, b1a, w2a, acc);
            acc = expert_quad(xp, w1b, b1b, w2b, acc);
            acc = expert_quad(xp, w1c, b1c, w2c, acc);
            acc = expert_quad(xp, w1d, b1d, w2d, acc);
            const float adj = fmaxf(acc.x + acc.y + b2e, 0.f);
            const float qe = q[rr][e];
            num[rr] = fmaf(qe, adj, num[rr]);
            den[rr] += qe;
        }
    }

#pragma unroll
    for (int rr = 0; rr < R; rr++) {
        if (ok[rr]) out[r[rr]] = __fdividef(num[rr], den[rr]);  // 0/0 -> NaN
    }
}

extern "C" void kernel_launch(void* const* d_in, const int* in_sizes, int n_in,
                              void* d_out, int out_size) {
    const float* x  = (const float*)d_in[0];
    const float* Wg = (const float*)d_in[1];
    const float* bg = (const float*)d_in[2];
    const float* W1 = (const float*)d_in[3];
    const float* b1 = (const float*)d_in[4];
    const float* W2 = (const float*)d_in[5];
    const float* b2 = (const float*)d_in[6];
    float* out = (float*)d_out;

    const int n = in_sizes[0] / 4;                  // rows
    const int per_iter = NT * R;
    const int blocks = (n + per_iter - 1) / per_iter;

    moe_kernel<<<blocks, NT>>>((const float4*)x, Wg, bg, W1, b1, W2, b2, out, n);
}